// round 4
// baseline (speedup 1.0000x reference)
#include <cuda_runtime.h>
#include <cuda_bf16.h>
#include <cstdint>

// ============================================================================
// QLoRABigNet on GB300 — int8 2-digit fixed-point GEMM (mma.sync m16n8k32.s8)
//   x,W quantized to 15.3-bit as 256*D1 + D0 with per-row scales.
//   y = sx*sw*(2^16*X1W1 + 2^8*(X1W0+X0W1))  [X0W0 dropped, ~2^-14 rel]
//   18x GEMM + 12x quant + 5x LN(+quant) + prep/split
// ============================================================================

#define NTOK    16384
#define DMODEL  1024
#define NLAYER  18
#define QMAX    32512.0f   // 127*256

// ---------------- scratch (device globals; no allocations allowed) ----------
__device__ int8_t g_W1[(size_t)NLAYER * DMODEL * DMODEL];
__device__ int8_t g_W0[(size_t)NLAYER * DMODEL * DMODEL];
__device__ float  g_SW[NLAYER * DMODEL];
__device__ int8_t g_X1[(size_t)NTOK * DMODEL];
__device__ int8_t g_X0[(size_t)NTOK * DMODEL];
__device__ float  g_SX[NTOK];
__device__ float  g_RES[(size_t)NTOK * DMODEL];   // residual stream (fp32)
__device__ float  g_TMP[(size_t)NTOK * DMODEL];   // fp32 activations (pre-quant/LN)
__device__ float  g_PART[(size_t)NTOK * 8];       // per-CTA row-max partials

// ---------------- helpers ----------------------------------------------------
__device__ __forceinline__ uint32_t smem_u32(const void* p) {
    uint32_t a;
    asm("{ .reg .u64 t; cvta.to.shared.u64 t, %1; cvt.u32.u64 %0, t; }"
        : "=r"(a) : "l"(p));
    return a;
}

__device__ __forceinline__ void ldsm_x4(uint32_t* r, uint32_t addr) {
    asm volatile("ldmatrix.sync.aligned.m8n8.x4.shared.b16 {%0,%1,%2,%3}, [%4];"
                 : "=r"(r[0]), "=r"(r[1]), "=r"(r[2]), "=r"(r[3]) : "r"(addr));
}

__device__ __forceinline__ void mma_s8(int* c, const uint32_t* a,
                                       uint32_t b0, uint32_t b1) {
    asm volatile(
        "mma.sync.aligned.m16n8k32.row.col.s32.s8.s8.s32 "
        "{%0,%1,%2,%3}, {%4,%5,%6,%7}, {%8,%9}, {%0,%1,%2,%3};"
        : "+r"(c[0]), "+r"(c[1]), "+r"(c[2]), "+r"(c[3])
        : "r"(a[0]), "r"(a[1]), "r"(a[2]), "r"(a[3]), "r"(b0), "r"(b1));
}

#define CP_ASYNC16(dst, src) \
    asm volatile("cp.async.cg.shared.global [%0], [%1], 16;" \
                 :: "r"(dst), "l"(src))
#define CP_COMMIT() asm volatile("cp.async.commit_group;" ::: "memory")
#define CP_WAIT(n)  asm volatile("cp.async.wait_group %0;" :: "n"(n) : "memory")

// quantize v*s -> (hi, lo) digits
__device__ __forceinline__ void qdigits(float v, float s, int8_t& hi, int8_t& lo) {
    int q = __float2int_rn(v * s);
    int h = (q + 128) >> 8;
    hi = (int8_t)h;
    lo = (int8_t)(q - (h << 8));
}

// ============================================================================
// Prep: W_eff = dequant4bit + B@A -> per-row scale + int8 digits
//   grid (64, 18), 256 threads. Each block: one layer, 16 output rows.
// ============================================================================
__global__ __launch_bounds__(256) void prep_weights(
    const int* __restrict__ qw, const float* __restrict__ scales,
    const float* __restrict__ lA, const float* __restrict__ lB)
{
    __shared__ float sB[16 * 32];
    __shared__ float sA[32 * 256];
    __shared__ unsigned smx[16];
    const int li = blockIdx.y;
    const int o0 = blockIdx.x * 16;
    const int tid = threadIdx.x;

    const float* Bl = lB + ((size_t)li * DMODEL + o0) * 32;
    for (int k = tid; k < 512; k += 256) sB[k] = Bl[k];
    if (tid < 16) smx[tid] = 0u;

    const float* Al = lA + (size_t)li * 32 * DMODEL;
    const int*   ql = qw + (size_t)li * DMODEL * DMODEL;
    const float* sc = scales + (size_t)li * DMODEL * 64;

    float wreg[4][16];
    float pmax[16];
    #pragma unroll
    for (int oo = 0; oo < 16; oo++) pmax[oo] = 0.0f;

    for (int ic = 0; ic < 4; ic++) {
        const int i0 = ic * 256;
        __syncthreads();
        for (int k = tid; k < 8192; k += 256) {
            int r = k >> 8, c = k & 255;
            sA[r * 256 + c] = Al[(size_t)r * DMODEL + i0 + c];
        }
        __syncthreads();
        const int i = i0 + tid;
        float d[16];
        #pragma unroll
        for (int oo = 0; oo < 16; oo++) d[oo] = 0.0f;
        #pragma unroll
        for (int r = 0; r < 32; r++) {
            float a = sA[r * 256 + tid];
            #pragma unroll
            for (int oo = 0; oo < 16; oo++) d[oo] += sB[oo * 32 + r] * a;
        }
        #pragma unroll
        for (int oo = 0; oo < 16; oo++) {
            const int o = o0 + oo;
            float qv = (float)ql[(size_t)o * DMODEL + i];
            float s  = sc[(size_t)o * 64 + (i >> 4)];
            float w  = (qv * (2.0f / 15.0f) - 1.0f) * s + d[oo];
            wreg[ic][oo] = w;
            pmax[oo] = fmaxf(pmax[oo], fabsf(w));
        }
    }
    __syncthreads();
    #pragma unroll
    for (int oo = 0; oo < 16; oo++)
        atomicMax(&smx[oo], __float_as_uint(pmax[oo]));
    __syncthreads();
    if (tid < 16)
        g_SW[li * DMODEL + o0 + tid] = __uint_as_float(smx[tid]) * (1.0f / QMAX);

    #pragma unroll
    for (int ic = 0; ic < 4; ic++) {
        const int i = ic * 256 + tid;
        #pragma unroll
        for (int oo = 0; oo < 16; oo++) {
            float mx = __uint_as_float(smx[oo]);
            float s = (mx > 0.0f) ? (QMAX / mx) : 0.0f;
            int8_t hi, lo;
            qdigits(wreg[ic][oo], s, hi, lo);
            size_t off = (size_t)(li * DMODEL + o0 + oo) * DMODEL + i;
            g_W1[off] = hi;
            g_W0[off] = lo;
        }
    }
}

// ============================================================================
// split_x: quantize initial x (block per row)
// ============================================================================
__global__ __launch_bounds__(256) void split_x(const float* __restrict__ x) {
    const int row = blockIdx.x;
    const int tid = threadIdx.x;
    const int wid = tid >> 5, lane = tid & 31;
    __shared__ float red[8];

    float v[4];
    #pragma unroll
    for (int k = 0; k < 4; k++) v[k] = x[(size_t)row * DMODEL + tid + k * 256];
    float m = fmaxf(fmaxf(fabsf(v[0]), fabsf(v[1])), fmaxf(fabsf(v[2]), fabsf(v[3])));
    #pragma unroll
    for (int o = 16; o > 0; o >>= 1) m = fmaxf(m, __shfl_xor_sync(0xFFFFFFFFu, m, o));
    if (lane == 0) red[wid] = m;
    __syncthreads();
    float mx = 0.0f;
    #pragma unroll
    for (int w = 0; w < 8; w++) mx = fmaxf(mx, red[w]);
    float s = (mx > 0.0f) ? (QMAX / mx) : 0.0f;
    if (tid == 0) g_SX[row] = mx * (1.0f / QMAX);
    #pragma unroll
    for (int k = 0; k < 4; k++) {
        int8_t hi, lo;
        qdigits(v[k], s, hi, lo);
        size_t off = (size_t)row * DMODEL + tid + k * 256;
        g_X1[off] = hi;
        g_X0[off] = lo;
    }
}

// ============================================================================
// Main GEMM: CTA 128x128, BK=32, 5-stage cp.async, int8 m16n8k32, 3 passes.
//   8 warps: warp_m = wid&1 (64 rows), warp_n = wid>>1 (32 cols)
//   SMEM tiles: 128 rows x 32B, 16B-chunk XOR swizzle for conflict-free ldsm
//   mode 0: y=relu(..)+  -> g_TMP + row-max partials (quant kernel follows)
//   mode 1: y=..+res     -> g_TMP (LN kernel follows)
//   mode 2: y=..+res     -> dout
// ============================================================================
#define BK 32
#define XT (128 * 32)              // 4096 B per tile
#define STAGEB (4 * XT)            // 16384 B
#define STAGES 5
#define GEMM_SMEM (STAGES * STAGEB)  // 81920 B
#define NCHUNK (DMODEL / BK)       // 32

__global__ __launch_bounds__(256, 1)
void qlora_gemm(int li, int mode,
                const float* __restrict__ bias,
                const float* __restrict__ res_ext, int useResExt,
                float* __restrict__ dout)
{
    extern __shared__ char smem[];
    const uint32_t sb = smem_u32(smem);
    const int tid = threadIdx.x;
    const int wid = tid >> 5;
    const int lane = tid & 31;
    const int warp_m = wid & 1;
    const int warp_n = wid >> 1;
    const int m0 = blockIdx.y * 128;
    const int n0 = blockIdx.x * 128;

    const char* srcb[4];
    srcb[0] = (const char*)(g_X1 + (size_t)m0 * DMODEL);
    srcb[1] = (const char*)(g_X0 + (size_t)m0 * DMODEL);
    srcb[2] = (const char*)(g_W1 + ((size_t)li * DMODEL + n0) * DMODEL);
    srcb[3] = (const char*)(g_W0 + ((size_t)li * DMODEL + n0) * DMODEL);

    // cp.async dst: row r (32B), half h(16B) -> swizzled 16B chunk
    const int strow = tid >> 1;
    const int sth   = tid & 1;
    const int stsw  = sth ^ (strow & 1) ^ ((strow >> 2) & 1);
    const uint32_t stoff = (uint32_t)(strow * 32 + stsw * 16);

    auto load_chunk = [&](int kc) {
        const uint32_t sbase = sb + (kc % STAGES) * STAGEB;
        #pragma unroll
        for (int t = 0; t < 4; t++) {
            const char* src = srcb[t] + (size_t)strow * DMODEL
                              + (size_t)kc * 32 + sth * 16;
            CP_ASYNC16(sbase + t * XT + stoff, src);
        }
        CP_COMMIT();
    };

    int acch[4][4][4], accm[4][4][4];
    #pragma unroll
    for (int a = 0; a < 4; a++)
        #pragma unroll
        for (int b = 0; b < 4; b++)
            #pragma unroll
            for (int q = 0; q < 4; q++) { acch[a][b][q] = 0; accm[a][b][q] = 0; }

    // ldsm addressing: swizzle sel is a per-lane constant
    const int lrow = lane & 15;
    const int lch  = lane >> 4;
    const int lsw  = (lrow & 1) ^ ((lrow >> 2) & 1);
    const uint32_t co   = (uint32_t)((lch ^ lsw) * 16);
    const uint32_t rowA = (uint32_t)((warp_m * 64 + lrow) * 32) + co;
    const uint32_t rowB = (uint32_t)((warp_n * 32 + lrow) * 32) + co;

    load_chunk(0); load_chunk(1); load_chunk(2); load_chunk(3);

    #pragma unroll 1
    for (int kc = 0; kc < NCHUNK; kc++) {
        CP_WAIT(3);
        __syncthreads();
        if (kc + 4 < NCHUNK) load_chunk(kc + 4);
        else CP_COMMIT();   // keep group count uniform

        const uint32_t base = sb + (kc % STAGES) * STAGEB;
        uint32_t fx1[4][4], fx0[4][4], fw1[2][4], fw0[2][4];
        #pragma unroll
        for (int nj = 0; nj < 2; nj++)
            ldsm_x4(fw1[nj], base + 2 * XT + rowB + nj * 512);
        #pragma unroll
        for (int mi = 0; mi < 4; mi++)
            ldsm_x4(fx1[mi], base + rowA + mi * 512);
        #pragma unroll
        for (int nj = 0; nj < 2; nj++)
            ldsm_x4(fw0[nj], base + 3 * XT + rowB + nj * 512);
        #pragma unroll
        for (int mi = 0; mi < 4; mi++)
            ldsm_x4(fx0[mi], base + XT + rowA + mi * 512);

        // pass 1: X1*W1 -> acch
        #pragma unroll
        for (int mi = 0; mi < 4; mi++)
            #pragma unroll
            for (int ni = 0; ni < 4; ni++) {
                const int nj = ni >> 1, s2 = ni & 1;
                mma_s8(acch[mi][ni], fx1[mi], fw1[nj][s2], fw1[nj][s2 + 2]);
            }
        // pass 2: X1*W0 -> accm
        #pragma unroll
        for (int mi = 0; mi < 4; mi++)
            #pragma unroll
            for (int ni = 0; ni < 4; ni++) {
                const int nj = ni >> 1, s2 = ni & 1;
                mma_s8(accm[mi][ni], fx1[mi], fw0[nj][s2], fw0[nj][s2 + 2]);
            }
        // pass 3: X0*W1 -> accm
        #pragma unroll
        for (int mi = 0; mi < 4; mi++)
            #pragma unroll
            for (int ni = 0; ni < 4; ni++) {
                const int nj = ni >> 1, s2 = ni & 1;
                mma_s8(accm[mi][ni], fx0[mi], fw1[nj][s2], fw1[nj][s2 + 2]);
            }
    }

    // ---------------- epilogue ------------------------------------------------
    __syncthreads();                     // smem stages no longer needed
    float* smaxbuf = (float*)smem;       // [4][128] row maxima (mode 0)

    const int grow = lane >> 2;
    const int gcol = (lane & 3) * 2;
    float sxv[4][2];
    #pragma unroll
    for (int mi = 0; mi < 4; mi++)
        #pragma unroll
        for (int h = 0; h < 2; h++)
            sxv[mi][h] = g_SX[m0 + warp_m * 64 + mi * 16 + h * 8 + grow];

    float rmax[4][2];
    #pragma unroll
    for (int mi = 0; mi < 4; mi++) { rmax[mi][0] = 0.0f; rmax[mi][1] = 0.0f; }

    float* outF = (mode == 2) ? dout : g_TMP;
    const float* resb = useResExt ? res_ext : g_RES;
    const float* swp = g_SW + li * DMODEL;

    #pragma unroll
    for (int mi = 0; mi < 4; mi++) {
        #pragma unroll
        for (int ni = 0; ni < 4; ni++) {
            const int col = n0 + warp_n * 32 + ni * 8 + gcol;
            float2 b2 = __ldg((const float2*)(bias + col));
            float sw0 = swp[col], sw1 = swp[col + 1];
            #pragma unroll
            for (int h = 0; h < 2; h++) {
                const int row = m0 + warp_m * 64 + mi * 16 + h * 8 + grow;
                const float sx = sxv[mi][h];
                float c0 = fmaf(65536.0f, (float)acch[mi][ni][2 * h],
                                256.0f * (float)accm[mi][ni][2 * h]);
                float c1 = fmaf(65536.0f, (float)acch[mi][ni][2 * h + 1],
                                256.0f * (float)accm[mi][ni][2 * h + 1]);
                float v0 = fmaf(c0, sx * sw0, b2.x);
                float v1 = fmaf(c1, sx * sw1, b2.y);
                if (mode == 0) {
                    v0 = fmaxf(v0, 0.0f);
                    v1 = fmaxf(v1, 0.0f);
                    rmax[mi][h] = fmaxf(rmax[mi][h], fmaxf(v0, v1));
                } else {
                    float2 r2 = __ldg((const float2*)(resb + (size_t)row * DMODEL + col));
                    v0 += r2.x; v1 += r2.y;
                }
                float2 o2; o2.x = v0; o2.y = v1;
                *reinterpret_cast<float2*>(outF + (size_t)row * DMODEL + col) = o2;
            }
        }
    }

    if (mode == 0) {
        #pragma unroll
        for (int mi = 0; mi < 4; mi++)
            #pragma unroll
            for (int h = 0; h < 2; h++) {
                float m = rmax[mi][h];
                m = fmaxf(m, __shfl_xor_sync(0xFFFFFFFFu, m, 1));
                m = fmaxf(m, __shfl_xor_sync(0xFFFFFFFFu, m, 2));
                if ((lane & 3) == 0)
                    smaxbuf[warp_n * 128 + warp_m * 64 + mi * 16 + h * 8 + grow] = m;
            }
        __syncthreads();
        if (tid < 128) {
            float m = fmaxf(fmaxf(smaxbuf[tid], smaxbuf[128 + tid]),
                            fmaxf(smaxbuf[256 + tid], smaxbuf[384 + tid]));
            g_PART[(size_t)(m0 + tid) * 8 + blockIdx.x] = m;
        }
    }
}

// ============================================================================
// quant: g_TMP row -> int8 digits + scale (block per row; relu layers)
// ============================================================================
__global__ __launch_bounds__(256) void quant_kernel() {
    const int row = blockIdx.x;
    const int tid = threadIdx.x;
    float m = 0.0f;
    #pragma unroll
    for (int j = 0; j < 8; j++) m = fmaxf(m, g_PART[(size_t)row * 8 + j]);
    float s = (m > 0.0f) ? (QMAX / m) : 0.0f;
    if (tid == 0) g_SX[row] = m * (1.0f / QMAX);
    #pragma unroll
    for (int k = 0; k < 4; k++) {
        size_t off = (size_t)row * DMODEL + tid + k * 256;
        int8_t hi, lo;
        qdigits(g_TMP[off], s, hi, lo);
        g_X1[off] = hi;
        g_X0[off] = lo;
    }
}

// ============================================================================
// LayerNorm (block per row): g_TMP -> g_RES (fp32) + int8 digits + scale
// ============================================================================
__global__ __launch_bounds__(256) void ln_kernel(
    const float* __restrict__ gamma, const float* __restrict__ beta)
{
    const int row = blockIdx.x;
    const int tid = threadIdx.x;
    const int wid = tid >> 5, lane = tid & 31;
    const float* in = g_TMP + (size_t)row * DMODEL;
    __shared__ float red[8];

    float v[4];
    #pragma unroll
    for (int k = 0; k < 4; k++) v[k] = in[tid + k * 256];

    float s = v[0] + v[1] + v[2] + v[3];
    #pragma unroll
    for (int o = 16; o > 0; o >>= 1) s += __shfl_xor_sync(0xFFFFFFFFu, s, o);
    if (lane == 0) red[wid] = s;
    __syncthreads();
    float tot = 0.0f;
    #pragma unroll
    for (int w = 0; w < 8; w++) tot += red[w];
    const float mean = tot * (1.0f / DMODEL);

    float sq = 0.0f;
    #pragma unroll
    for (int k = 0; k < 4; k++) { float d = v[k] - mean; sq += d * d; }
    #pragma unroll
    for (int o = 16; o > 0; o >>= 1) sq += __shfl_xor_sync(0xFFFFFFFFu, sq, o);
    __syncthreads();
    if (lane == 0) red[wid] = sq;
    __syncthreads();
    float vtot = 0.0f;
    #pragma unroll
    for (int w = 0; w < 8; w++) vtot += red[w];
    const float r = rsqrtf(vtot * (1.0f / DMODEL) + 1e-5f);

    float y[4];
    float pm = 0.0f;
    #pragma unroll
    for (int k = 0; k < 4; k++) {
        const int c = tid + k * 256;
        y[k] = (v[k] - mean) * r * gamma[c] + beta[c];
        g_RES[(size_t)row * DMODEL + c] = y[k];
        pm = fmaxf(pm, fabsf(y[k]));
    }
    #pragma unroll
    for (int o = 16; o > 0; o >>= 1) pm = fmaxf(pm, __shfl_xor_sync(0xFFFFFFFFu, pm, o));
    __syncthreads();
    if (lane == 0) red[wid] = pm;
    __syncthreads();
    float mx = 0.0f;
    #pragma unroll
    for (int w = 0; w < 8; w++) mx = fmaxf(mx, red[w]);
    float qs = (mx > 0.0f) ? (QMAX / mx) : 0.0f;
    if (tid == 0) g_SX[row] = mx * (1.0f / QMAX);
    #pragma unroll
    for (int k = 0; k < 4; k++) {
        const int c = tid + k * 256;
        int8_t hi, lo;
        qdigits(y[k], qs, hi, lo);
        g_X1[(size_t)row * DMODEL + c] = hi;
        g_X0[(size_t)row * DMODEL + c] = lo;
    }
}

// ============================================================================
// Launch
// ============================================================================
extern "C" void kernel_launch(void* const* d_in, const int* in_sizes, int n_in,
                              void* d_out, int out_size)
{
    (void)in_sizes; (void)n_in; (void)out_size;
    const float* x      = (const float*)d_in[0];
    const int*   qw     = (const int*)d_in[1];
    const float* scales = (const float*)d_in[2];
    const float* bias   = (const float*)d_in[3];
    const float* lA     = (const float*)d_in[4];
    const float* lB     = (const float*)d_in[5];
    const float* lng    = (const float*)d_in[6];
    const float* lnb    = (const float*)d_in[7];
    float* out = (float*)d_out;

    cudaFuncSetAttribute(qlora_gemm, cudaFuncAttributeMaxDynamicSharedMemorySize,
                         GEMM_SMEM);

    prep_weights<<<dim3(64, 18), 256>>>(qw, scales, lA, lB);
    split_x<<<NTOK, 256>>>(x);

    for (int blk = 0; blk < 6; blk++) {
        for (int j = 0; j < 3; j++) {
            const int li = blk * 3 + j;
            if (j < 2) {
                qlora_gemm<<<dim3(8, 128), 256, GEMM_SMEM>>>(
                    li, 0, bias + li * DMODEL, nullptr, 0, nullptr);
                quant_kernel<<<NTOK, 256>>>();
            } else {
                const int mode = (blk == 5) ? 2 : 1;
                qlora_gemm<<<dim3(8, 128), 256, GEMM_SMEM>>>(
                    li, mode, bias + li * DMODEL, x, (blk == 0) ? 1 : 0, out);
            }
        }
        if (blk < 5) ln_kernel<<<NTOK, 256>>>(lng + blk * DMODEL, lnb + blk * DMODEL);
    }
}

// round 5
// speedup vs baseline: 2.7928x; 2.7928x over previous
#include <cuda_runtime.h>
#include <cuda_bf16.h>
#include <cstdint>

// ============================================================================
// QLoRABigNet on GB300 (mma.sync bf16 path; tcgen05 blocked by non-'a' PTX target)
//   prep:  W_eff[l] = dequant4(qw,scales) + B@A  -> split bf16 hi/lo
//   18x GEMM (mma.sync m16n8k16 bf16, 3-term split, fp32 accum) + fused epilogue
//   5x LayerNorm
// R4: stage-cycle unrolled mainloop (immediate smem bases), hoisted cp.async
//     address math -> cut ALU issue pressure.
// ============================================================================

#define NTOK    16384
#define DMODEL  1024
#define NLAYER  18

__device__ __nv_bfloat16 g_WH[(size_t)NLAYER * DMODEL * DMODEL];
__device__ __nv_bfloat16 g_WL[(size_t)NLAYER * DMODEL * DMODEL];
__device__ __nv_bfloat16 g_XH0[(size_t)NTOK * DMODEL];
__device__ __nv_bfloat16 g_XL0[(size_t)NTOK * DMODEL];
__device__ __nv_bfloat16 g_XH1[(size_t)NTOK * DMODEL];
__device__ __nv_bfloat16 g_XL1[(size_t)NTOK * DMODEL];
__device__ float         g_RES[(size_t)NTOK * DMODEL];
__device__ float         g_TMP[(size_t)NTOK * DMODEL];

// ---------------- helpers ----------------------------------------------------
__device__ __forceinline__ uint32_t smem_u32(const void* p) {
    uint32_t a;
    asm("{ .reg .u64 t; cvta.to.shared.u64 t, %1; cvt.u32.u64 %0, t; }"
        : "=r"(a) : "l"(p));
    return a;
}

__device__ __forceinline__ void ldsm_x4(uint32_t* r, uint32_t addr) {
    asm volatile("ldmatrix.sync.aligned.m8n8.x4.shared.b16 {%0,%1,%2,%3}, [%4];"
                 : "=r"(r[0]), "=r"(r[1]), "=r"(r[2]), "=r"(r[3]) : "r"(addr));
}

__device__ __forceinline__ void mma_bf16(float* c, const uint32_t* a,
                                         uint32_t b0, uint32_t b1) {
    asm volatile(
        "mma.sync.aligned.m16n8k16.row.col.f32.bf16.bf16.f32 "
        "{%0,%1,%2,%3}, {%4,%5,%6,%7}, {%8,%9}, {%0,%1,%2,%3};"
        : "+f"(c[0]), "+f"(c[1]), "+f"(c[2]), "+f"(c[3])
        : "r"(a[0]), "r"(a[1]), "r"(a[2]), "r"(a[3]), "r"(b0), "r"(b1));
}

#define CP_ASYNC16(dst, src) \
    asm volatile("cp.async.cg.shared.global [%0], [%1], 16;" \
                 :: "r"(dst), "l"(src))
#define CP_COMMIT() asm volatile("cp.async.commit_group;" ::: "memory")
#define CP_WAIT(n)  asm volatile("cp.async.wait_group %0;" :: "n"(n) : "memory")

// ============================================================================
// Prep: W_eff = dequant4bit + B@A, split into bf16 hi/lo
// ============================================================================
__global__ __launch_bounds__(256) void prep_weights(
    const int* __restrict__ qw, const float* __restrict__ scales,
    const float* __restrict__ lA, const float* __restrict__ lB)
{
    __shared__ float sB[16 * 32];
    __shared__ float sA[32 * 256];
    const int li = blockIdx.y;
    const int o0 = blockIdx.x * 16;
    const int tid = threadIdx.x;

    const float* Bl = lB + ((size_t)li * DMODEL + o0) * 32;
    for (int k = tid; k < 512; k += 256) sB[k] = Bl[k];

    const float* Al = lA + (size_t)li * 32 * DMODEL;
    const int*   ql = qw + (size_t)li * DMODEL * DMODEL;
    const float* sc = scales + (size_t)li * DMODEL * 64;
    __nv_bfloat16* wh = g_WH + (size_t)li * DMODEL * DMODEL;
    __nv_bfloat16* wl = g_WL + (size_t)li * DMODEL * DMODEL;

    for (int ic = 0; ic < 4; ic++) {
        const int i0 = ic * 256;
        __syncthreads();
        for (int k = tid; k < 8192; k += 256) {
            int r = k >> 8, c = k & 255;
            sA[r * 256 + c] = Al[(size_t)r * DMODEL + i0 + c];
        }
        __syncthreads();
        const int i = i0 + tid;
        float d[16];
        #pragma unroll
        for (int oo = 0; oo < 16; oo++) d[oo] = 0.0f;
        #pragma unroll
        for (int r = 0; r < 32; r++) {
            float a = sA[r * 256 + tid];
            #pragma unroll
            for (int oo = 0; oo < 16; oo++) d[oo] += sB[oo * 32 + r] * a;
        }
        #pragma unroll
        for (int oo = 0; oo < 16; oo++) {
            const int o = o0 + oo;
            float qv = (float)ql[(size_t)o * DMODEL + i];
            float s  = sc[(size_t)o * 64 + (i >> 4)];
            float w  = (qv * (2.0f / 15.0f) - 1.0f) * s + d[oo];
            __nv_bfloat16 h = __float2bfloat16_rn(w);
            float lo = w - __bfloat162float(h);
            wh[(size_t)o * DMODEL + i] = h;
            wl[(size_t)o * DMODEL + i] = __float2bfloat16_rn(lo);
        }
    }
}

// ============================================================================
// Split initial x into bf16 hi/lo (buffer set 0)
// ============================================================================
__global__ __launch_bounds__(256) void split_x(const float* __restrict__ x) {
    size_t i = ((size_t)blockIdx.x * 256 + threadIdx.x) * 4;
    float4 v = *reinterpret_cast<const float4*>(x + i);
    float vv[4] = {v.x, v.y, v.z, v.w};
    #pragma unroll
    for (int k = 0; k < 4; k++) {
        __nv_bfloat16 h = __float2bfloat16_rn(vv[k]);
        g_XH0[i + k] = h;
        g_XL0[i + k] = __float2bfloat16_rn(vv[k] - __bfloat162float(h));
    }
}

// ============================================================================
// Main GEMM: CTA tile 128x128, BK=32, 3-stage cp.async, mma.sync bf16 3-term.
//   8 warps: warp_m = wid&1 (64 rows), warp_n = wid>>1 (32 cols)
//   SMEM: 64B rows with XOR swizzle -> conflict-free; 96KB/CTA -> 2 CTAs/SM
// ============================================================================
#define BM 128
#define BN 128
#define BK 32
#define ROWB 64
#define TILEB (128 * ROWB)        // 8192 B
#define STAGEB (4 * TILEB)        // 32768 B
#define GEMM_SMEM (3 * STAGEB)    // 98304 B
#define NCHUNK (DMODEL / BK)      // 32

__global__ __launch_bounds__(256, 2)
void qlora_gemm(int li, int inSel, int mode,
                const float* __restrict__ bias,
                const float* __restrict__ res_ext, int useResExt,
                float* __restrict__ dout)
{
    extern __shared__ char smem[];
    const uint32_t sb = smem_u32(smem);
    const int tid = threadIdx.x;
    const int wid = tid >> 5;
    const int lane = tid & 31;
    const int warp_m = wid & 1;
    const int warp_n = wid >> 1;
    const int m0 = blockIdx.y * BM;
    const int n0 = blockIdx.x * BN;

    const __nv_bfloat16* xh = inSel ? g_XH1 : g_XH0;
    const __nv_bfloat16* xl = inSel ? g_XL1 : g_XL0;
    const __nv_bfloat16* whp = g_WH + (size_t)li * DMODEL * DMODEL;
    const __nv_bfloat16* wlp = g_WL + (size_t)li * DMODEL * DMODEL;

    // --------- hoisted cp.async addressing ----------------------------------
    // thread handles 8 vectors: it=0..7, tile t=it>>1, row=(it&1)*64 + (tid>>2),
    // col chunk c=tid&3; swizzled chunk cp = c ^ ((r0>>1)&3) (row-parity invariant)
    const int r0 = tid >> 2;
    const int c4 = tid & 3;
    const uint32_t dloc = (uint32_t)(r0 * ROWB + (c4 ^ ((r0 >> 1) & 3)) * 16);
    const char* P0 = (const char*)(xh + (size_t)m0 * DMODEL) + r0 * 2048 + c4 * 16;
    const char* P1 = (const char*)(xl + (size_t)m0 * DMODEL) + r0 * 2048 + c4 * 16;
    const char* P2 = (const char*)(whp + (size_t)n0 * DMODEL) + r0 * 2048 + c4 * 16;
    const char* P3 = (const char*)(wlp + (size_t)n0 * DMODEL) + r0 * 2048 + c4 * 16;

    // per-lane ldmatrix components (swizzle sel depends only on lane&15)
    const int lrow = lane & 15;
    const int lch  = lane >> 4;
    const int sel  = (lrow >> 1) & 3;
    const uint32_t co0  = (uint32_t)((lch ^ sel) * 16);
    const uint32_t co1  = (uint32_t)(((lch + 2) ^ sel) * 16);
    const uint32_t rowA = (uint32_t)((warp_m * 64 + lrow) * ROWB);
    const uint32_t rowB = (uint32_t)((warp_n * 32 + lrow) * ROWB);

    float acc[4][4][4];
    #pragma unroll
    for (int a = 0; a < 4; a++)
        #pragma unroll
        for (int b = 0; b < 4; b++)
            #pragma unroll
            for (int q = 0; q < 4; q++) acc[a][b][q] = 0.0f;

// load chunk kc into stage ST (compile-time literal)
#define LOADC(kc, ST) do {                                                     \
    const uint32_t _sb2 = sb + (ST) * STAGEB + dloc;                           \
    const size_t _ko = (size_t)(kc) * 64;                                      \
    CP_ASYNC16(_sb2,                          P0 + _ko);                       \
    CP_ASYNC16(_sb2 + 4096,                   P0 + _ko + 131072);              \
    CP_ASYNC16(_sb2 + TILEB,                  P1 + _ko);                       \
    CP_ASYNC16(_sb2 + TILEB + 4096,           P1 + _ko + 131072);              \
    CP_ASYNC16(_sb2 + 2 * TILEB,              P2 + _ko);                       \
    CP_ASYNC16(_sb2 + 2 * TILEB + 4096,       P2 + _ko + 131072);              \
    CP_ASYNC16(_sb2 + 3 * TILEB,              P3 + _ko);                       \
    CP_ASYNC16(_sb2 + 3 * TILEB + 4096,       P3 + _ko + 131072);              \
    CP_COMMIT();                                                               \
} while (0)

#define MMASTEP(BASE, CO) do {                                                 \
    uint32_t fxh[4][4], fxl[4][4], fwh[2][4], fwl[2][4];                       \
    _Pragma("unroll")                                                          \
    for (int mi = 0; mi < 4; mi++)                                             \
        ldsm_x4(fxh[mi], (BASE) + rowA + mi * (16 * ROWB) + (CO));             \
    _Pragma("unroll")                                                          \
    for (int nj = 0; nj < 2; nj++)                                             \
        ldsm_x4(fwh[nj], (BASE) + 2 * TILEB + rowB + nj * (16 * ROWB) + (CO)); \
    _Pragma("unroll")                                                          \
    for (int mi = 0; mi < 4; mi++)                                             \
        ldsm_x4(fxl[mi], (BASE) + TILEB + rowA + mi * (16 * ROWB) + (CO));     \
    _Pragma("unroll")                                                          \
    for (int nj = 0; nj < 2; nj++)                                             \
        ldsm_x4(fwl[nj], (BASE) + 3 * TILEB + rowB + nj * (16 * ROWB) + (CO)); \
    _Pragma("unroll")                                                          \
    for (int mi = 0; mi < 4; mi++)                                             \
        _Pragma("unroll")                                                      \
        for (int ni = 0; ni < 4; ni++) {                                       \
            const int nj = ni >> 1, s2 = ni & 1;                               \
            mma_bf16(acc[mi][ni], fxh[mi], fwh[nj][s2], fwh[nj][s2 + 2]);      \
        }                                                                      \
    _Pragma("unroll")                                                          \
    for (int mi = 0; mi < 4; mi++)                                             \
        _Pragma("unroll")                                                      \
        for (int ni = 0; ni < 4; ni++) {                                       \
            const int nj = ni >> 1, s2 = ni & 1;                               \
            mma_bf16(acc[mi][ni], fxh[mi], fwl[nj][s2], fwl[nj][s2 + 2]);      \
        }                                                                      \
    _Pragma("unroll")                                                          \
    for (int mi = 0; mi < 4; mi++)                                             \
        _Pragma("unroll")                                                      \
        for (int ni = 0; ni < 4; ni++) {                                       \
            const int nj = ni >> 1, s2 = ni & 1;                               \
            mma_bf16(acc[mi][ni], fxl[mi], fwh[nj][s2], fwh[nj][s2 + 2]);      \
        }                                                                      \
} while (0)

// full chunk: wait, sync, prefetch kc+2 (or dummy), 2 mma steps. ST literal.
#define CHUNK(kc, ST, DO_LOAD) do {                                            \
    CP_WAIT(1);                                                                \
    __syncthreads();                                                           \
    if (DO_LOAD) { LOADC((kc) + 2, ((ST) + 2) % 3); } else { CP_COMMIT(); }    \
    const uint32_t _base = sb + (ST) * STAGEB;                                 \
    MMASTEP(_base, co0);                                                       \
    MMASTEP(_base, co1);                                                       \
} while (0)

    LOADC(0, 0);
    LOADC(1, 1);

    #pragma unroll 1
    for (int k3 = 0; k3 < 30; k3 += 3) {
        CHUNK(k3 + 0, 0, true);
        CHUNK(k3 + 1, 1, true);
        CHUNK(k3 + 2, 2, true);
    }
    CHUNK(30, 0, false);
    CHUNK(31, 1, false);

#undef CHUNK
#undef MMASTEP
#undef LOADC

    // ---------------- epilogue ------------------------------------------------
    const int grow = lane >> 2;
    const int gcol = (lane & 3) * 2;
    __nv_bfloat16* outH = inSel ? g_XH0 : g_XH1;
    __nv_bfloat16* outL = inSel ? g_XL0 : g_XL1;
    float* outF = (mode == 2) ? dout : g_TMP;
    const float* resb = useResExt ? res_ext : g_RES;

    #pragma unroll
    for (int mi = 0; mi < 4; mi++) {
        const int r0e = m0 + warp_m * 64 + mi * 16 + grow;
        #pragma unroll
        for (int ni = 0; ni < 4; ni++) {
            const int col = n0 + warp_n * 32 + ni * 8 + gcol;
            float2 b2 = __ldg((const float2*)(bias + col));
            #pragma unroll
            for (int half = 0; half < 2; half++) {
                const int row = r0e + half * 8;
                float v0 = acc[mi][ni][half * 2 + 0] + b2.x;
                float v1 = acc[mi][ni][half * 2 + 1] + b2.y;
                if (mode == 0) {
                    v0 = fmaxf(v0, 0.0f);
                    v1 = fmaxf(v1, 0.0f);
                    __nv_bfloat16 h0 = __float2bfloat16_rn(v0);
                    __nv_bfloat16 h1 = __float2bfloat16_rn(v1);
                    __nv_bfloat162 hp; hp.x = h0; hp.y = h1;
                    __nv_bfloat162 lp;
                    lp.x = __float2bfloat16_rn(v0 - __bfloat162float(h0));
                    lp.y = __float2bfloat16_rn(v1 - __bfloat162float(h1));
                    *reinterpret_cast<__nv_bfloat162*>(outH + (size_t)row * DMODEL + col) = hp;
                    *reinterpret_cast<__nv_bfloat162*>(outL + (size_t)row * DMODEL + col) = lp;
                } else {
                    float2 r2 = __ldg((const float2*)(resb + (size_t)row * DMODEL + col));
                    float2 o2;
                    o2.x = v0 + r2.x;
                    o2.y = v1 + r2.y;
                    *reinterpret_cast<float2*>(outF + (size_t)row * DMODEL + col) = o2;
                }
            }
        }
    }
}

// ============================================================================
// LayerNorm: 1 block (256 thr) per token row
// ============================================================================
__global__ __launch_bounds__(256) void ln_kernel(
    const float* __restrict__ gamma, const float* __restrict__ beta)
{
    const int row = blockIdx.x;
    const int tid = threadIdx.x;
    const int wid = tid >> 5, lane = tid & 31;
    const float* in = g_TMP + (size_t)row * DMODEL;

    float v[4];
    #pragma unroll
    for (int k = 0; k < 4; k++) v[k] = in[tid + k * 256];

    __shared__ float red[8];
    float s = v[0] + v[1] + v[2] + v[3];
    #pragma unroll
    for (int o = 16; o > 0; o >>= 1) s += __shfl_xor_sync(0xFFFFFFFFu, s, o);
    if (lane == 0) red[wid] = s;
    __syncthreads();
    float tot = 0.0f;
    #pragma unroll
    for (int w = 0; w < 8; w++) tot += red[w];
    const float mean = tot * (1.0f / DMODEL);

    float sq = 0.0f;
    #pragma unroll
    for (int k = 0; k < 4; k++) { float d = v[k] - mean; sq += d * d; }
    #pragma unroll
    for (int o = 16; o > 0; o >>= 1) sq += __shfl_xor_sync(0xFFFFFFFFu, sq, o);
    __syncthreads();
    if (lane == 0) red[wid] = sq;
    __syncthreads();
    float vtot = 0.0f;
    #pragma unroll
    for (int w = 0; w < 8; w++) vtot += red[w];
    const float r = rsqrtf(vtot * (1.0f / DMODEL) + 1e-5f);

    #pragma unroll
    for (int k = 0; k < 4; k++) {
        const int c = tid + k * 256;
        float y = (v[k] - mean) * r * gamma[c] + beta[c];
        g_RES[(size_t)row * DMODEL + c] = y;
        __nv_bfloat16 h = __float2bfloat16_rn(y);
        g_XH0[(size_t)row * DMODEL + c] = h;
        g_XL0[(size_t)row * DMODEL + c] = __float2bfloat16_rn(y - __bfloat162float(h));
    }
}

// ============================================================================
// Launch
// ============================================================================
extern "C" void kernel_launch(void* const* d_in, const int* in_sizes, int n_in,
                              void* d_out, int out_size)
{
    (void)in_sizes; (void)n_in; (void)out_size;
    const float* x      = (const float*)d_in[0];
    const int*   qw     = (const int*)d_in[1];
    const float* scales = (const float*)d_in[2];
    const float* bias   = (const float*)d_in[3];
    const float* lA     = (const float*)d_in[4];
    const float* lB     = (const float*)d_in[5];
    const float* lng    = (const float*)d_in[6];
    const float* lnb    = (const float*)d_in[7];
    float* out = (float*)d_out;

    cudaFuncSetAttribute(qlora_gemm, cudaFuncAttributeMaxDynamicSharedMemorySize,
                         GEMM_SMEM);

    prep_weights<<<dim3(64, 18), 256>>>(qw, scales, lA, lB);
    split_x<<<(NTOK * DMODEL) / 1024, 256>>>(x);

    int inSel = 0;
    for (int blk = 0; blk < 6; blk++) {
        for (int j = 0; j < 3; j++) {
            const int li = blk * 3 + j;
            if (j < 2) {
                qlora_gemm<<<dim3(8, 128), 256, GEMM_SMEM>>>(
                    li, inSel, 0, bias + li * DMODEL, nullptr, 0, nullptr);
                inSel ^= 1;
            } else {
                const int mode = (blk == 5) ? 2 : 1;
                qlora_gemm<<<dim3(8, 128), 256, GEMM_SMEM>>>(
                    li, inSel, mode, bias + li * DMODEL, x, (blk == 0) ? 1 : 0, out);
            }
        }
        if (blk < 5) ln_kernel<<<NTOK, 256>>>(lng + blk * DMODEL, lnb + blk * DMODEL);
    }
}